// round 1
// baseline (speedup 1.0000x reference)
#include <cuda_runtime.h>
#include <cstdint>

#define NL 50
#define ND 64
#define NROWS 50000
#define TOTROWS 100000
#define RS 68            // smem row stride (floats): conflict-free rows & cols, 16B-aligned
#define SSTRIDE 52       // padded stride for S scratch

// softmax(srt) denominator: sum_{m=0}^{49} e^{-m} = 1.5819767068693265; this is 1/that
#define INV_C 0.63212055882855767841f

__device__ float g_S[(size_t)TOTROWS * SSTRIDE];   // te-dot scratch  (~20.8 MB)
__device__ float g_H[(size_t)TOTROWS * ND];        // attention output scratch (25.6 MB)

// ------------------------------------------------------------------
// Kernel 0: S[row][k] = <dst_h[row], te[k]>  for k=0..49
// ------------------------------------------------------------------
__global__ __launch_bounds__(128) void te_dot_kernel(
    const float* __restrict__ user_h, const float* __restrict__ item_h,
    const float* __restrict__ u_te,   const float* __restrict__ i_te)
{
    __shared__ float4 s_te[NL * 16];     // 50 x 64 floats = 12.8 KB
    const int side = blockIdx.y;
    const float* hsrc = side == 0 ? user_h : item_h;
    const float* te   = side == 0 ? u_te   : i_te;

    for (int i = threadIdx.x; i < NL * 16; i += 128)
        s_te[i] = ((const float4*)te)[i];
    __syncthreads();

    const int n = blockIdx.x * 128 + threadIdx.x;
    if (n >= NROWS) return;

    float4 h4[16];
    const float4* hrow = (const float4*)(hsrc + (size_t)n * ND);
#pragma unroll
    for (int c = 0; c < 16; c++) h4[c] = hrow[c];

    float* Srow = g_S + ((size_t)side * NROWS + n) * SSTRIDE;
#pragma unroll 2
    for (int k = 0; k < NL; k++) {
        float acc = 0.f;
#pragma unroll
        for (int c = 0; c < 16; c++) {
            float4 t4 = s_te[k * 16 + c];
            acc += h4[c].x * t4.x + h4[c].y * t4.y + h4[c].z * t4.z + h4[c].w * t4.w;
        }
        Srow[k] = acc;
    }
}

// ------------------------------------------------------------------
// Kernel 1: per-row attention.  1 block (64 threads) per destination row.
// ------------------------------------------------------------------
__global__ __launch_bounds__(64, 12) void attn_kernel(
    const float* __restrict__ user_h, const float* __restrict__ item_h,
    const int* __restrict__ u_nbr, const int* __restrict__ u_tim,
    const int* __restrict__ i_nbr, const int* __restrict__ i_tim)
{
    __shared__ float s_nbr[NL * RS];   // 13.6 KB neighbor tile
    __shared__ float s_dst[ND];
    __shared__ int   s_idx[NL];
    __shared__ int   s_tim[52];
    __shared__ int   s_srt[NL];
    __shared__ float s_S[NL];
    __shared__ float s_g[52];
    __shared__ float s_alpha[52];

    const int row = blockIdx.x;
    const int t = threadIdx.x;
    const bool uside = row < NROWS;
    const int n = uside ? row : row - NROWS;
    const float* dst = (uside ? user_h : item_h) + (size_t)n * ND;
    const float* src = uside ? item_h : user_h;
    const int* nbr = (uside ? u_nbr : i_nbr) + (size_t)n * NL;
    const int* tim = (uside ? u_tim : i_tim) + (size_t)n * NL;
    const float* Srow = g_S + (size_t)row * SSTRIDE;

    s_dst[t] = dst[t];
    if (t < NL) {
        s_idx[t] = nbr[t];
        s_tim[t] = tim[t];
        s_S[t]   = Srow[t];
    } else if (t < 52) {
        s_tim[t]   = 0x7fffffff;   // pad: never "less" and never ties real times
        s_g[t]     = -1e30f;       // pad for max loop
        s_alpha[t] = 0.f;          // pad for sum loop
    }
    __syncthreads();

    // --- pass A: gather 50 neighbor rows (float4, coalesced) into smem ---
    const float4* src4 = (const float4*)src;
#pragma unroll
    for (int i = 0; i < 13; i++) {
        int f = i * 64 + t;                 // 800 float4 elements total
        if (f < NL * 16) {
            int l = f >> 4, c = f & 15;
            float4 v = __ldg(&src4[(size_t)s_idx[l] * 16 + c]);
            *(float4*)&s_nbr[l * RS + c * 4] = v;
        }
    }

    // --- rank / srt (stable argsort semantics), thread l handles slot l ---
    int ro = 0;
    if (t < NL) {
        const int tl = s_tim[t];
        int r = 0;
#pragma unroll
        for (int i = 0; i < 13; i++) {
            int4 v = ((const int4*)s_tim)[i];
            int j = 4 * i;
            r += (v.x < tl) | ((v.x == tl) & (j     < t));
            r += (v.y < tl) | ((v.y == tl) & (j + 1 < t));
            r += (v.z < tl) | ((v.z == tl) & (j + 2 < t));
            r += (v.w < tl) | ((v.w == tl) & (j + 3 < t));
        }
        s_srt[r] = t;          // srt = inverse permutation of rank
        ro = NL - 1 - r;       // re_order
    }
    __syncthreads();

    // --- pass B: e[l] = (<nbr_l, dst> + S[ro_l]) * L/sqrt(D);  g = e * p ---
    if (t < NL) {
        const float4* rowp = (const float4*)&s_nbr[t * RS];
        const float4* d4 = (const float4*)s_dst;
        float acc = 0.f;
#pragma unroll
        for (int c = 0; c < 16; c++) {
            float4 a = rowp[c], b = d4[c];
            acc += a.x * b.x + a.y * b.y + a.z * b.z + a.w * b.w;
        }
        float e = (acc + s_S[ro]) * 6.25f;                       // 50/sqrt(64)
        float p = expf((float)s_srt[t] - 49.0f) * INV_C;         // rank prior
        s_g[t] = e * p;
    }
    __syncthreads();

    // --- softmax over g (every thread computes redundantly from smem) ---
    float m = -1e30f;
#pragma unroll
    for (int i = 0; i < 13; i++) {
        float4 g = ((const float4*)s_g)[i];
        m = fmaxf(m, fmaxf(fmaxf(g.x, g.y), fmaxf(g.z, g.w)));
    }
    if (t < NL) s_alpha[t] = expf(s_g[t] - m);
    __syncthreads();
    float sum = 0.f;
#pragma unroll
    for (int i = 0; i < 13; i++) {
        float4 a = ((const float4*)s_alpha)[i];
        sum += a.x + a.y + a.z + a.w;
    }
    const float inv = 1.0f / sum;

    // --- pass C: h[t] = sum_l alpha[l] * nbr[l][t]  (column reads, conflict-free) ---
    float h = 0.f;
#pragma unroll
    for (int i = 0; i < 12; i++) {
        float4 a = ((const float4*)s_alpha)[i];
        int l = 4 * i;
        h += a.x * s_nbr[(l    ) * RS + t];
        h += a.y * s_nbr[(l + 1) * RS + t];
        h += a.z * s_nbr[(l + 2) * RS + t];
        h += a.w * s_nbr[(l + 3) * RS + t];
    }
    h += s_alpha[48] * s_nbr[48 * RS + t];
    h += s_alpha[49] * s_nbr[49 * RS + t];

    g_H[(size_t)row * ND + t] = h * inv;
}

// ------------------------------------------------------------------
// Kernel 2: out = relu(H @ W1 + b1) @ W2 + b2   (thread-per-row, W in smem)
// ------------------------------------------------------------------
__global__ __launch_bounds__(128) void mlp_kernel(
    const float* __restrict__ W1u, const float* __restrict__ b1u,
    const float* __restrict__ W2u, const float* __restrict__ b2u,
    const float* __restrict__ W1i, const float* __restrict__ b1i,
    const float* __restrict__ W2i, const float* __restrict__ b2i,
    float* __restrict__ out)
{
    __shared__ float4 sW1[ND * 16];
    __shared__ float4 sW2[ND * 16];
    __shared__ float4 sb1[16];
    __shared__ float4 sb2[16];

    const int side = blockIdx.y;
    const float* W1 = side ? W1i : W1u;
    const float* W2 = side ? W2i : W2u;
    const float* b1 = side ? b1i : b1u;
    const float* b2 = side ? b2i : b2u;

    for (int i = threadIdx.x; i < ND * 16; i += 128) {
        sW1[i] = ((const float4*)W1)[i];
        sW2[i] = ((const float4*)W2)[i];
    }
    if (threadIdx.x < 16) {
        sb1[threadIdx.x] = ((const float4*)b1)[threadIdx.x];
        sb2[threadIdx.x] = ((const float4*)b2)[threadIdx.x];
    }
    __syncthreads();

    const int n = blockIdx.x * 128 + threadIdx.x;
    if (n >= NROWS) return;
    const size_t grow = (size_t)side * NROWS + n;

    float hreg[ND];
    const float4* Hrow = (const float4*)(g_H + grow * ND);
#pragma unroll
    for (int c = 0; c < 16; c++) ((float4*)hreg)[c] = Hrow[c];

    float4 o1[16];
#pragma unroll
    for (int c = 0; c < 16; c++) o1[c] = sb1[c];
#pragma unroll
    for (int k = 0; k < ND; k++) {
        float hk = hreg[k];
#pragma unroll
        for (int c = 0; c < 16; c++) {
            float4 w = sW1[k * 16 + c];
            o1[c].x += hk * w.x; o1[c].y += hk * w.y;
            o1[c].z += hk * w.z; o1[c].w += hk * w.w;
        }
    }
    float o1f[ND];
#pragma unroll
    for (int c = 0; c < 16; c++) {
        o1f[4 * c + 0] = fmaxf(o1[c].x, 0.f);
        o1f[4 * c + 1] = fmaxf(o1[c].y, 0.f);
        o1f[4 * c + 2] = fmaxf(o1[c].z, 0.f);
        o1f[4 * c + 3] = fmaxf(o1[c].w, 0.f);
    }

    float4 o2[16];
#pragma unroll
    for (int c = 0; c < 16; c++) o2[c] = sb2[c];
#pragma unroll
    for (int k = 0; k < ND; k++) {
        float hk = o1f[k];
#pragma unroll
        for (int c = 0; c < 16; c++) {
            float4 w = sW2[k * 16 + c];
            o2[c].x += hk * w.x; o2[c].y += hk * w.y;
            o2[c].z += hk * w.z; o2[c].w += hk * w.w;
        }
    }

    float4* orow = (float4*)(out + grow * ND);
#pragma unroll
    for (int c = 0; c < 16; c++) orow[c] = o2[c];
}

// ------------------------------------------------------------------
extern "C" void kernel_launch(void* const* d_in, const int* in_sizes, int n_in,
                              void* d_out, int out_size)
{
    const float* user_h = (const float*)d_in[0];
    const float* item_h = (const float*)d_in[1];
    const float* u_te   = (const float*)d_in[2];
    const float* i_te   = (const float*)d_in[3];
    const float* Wu1 = (const float*)d_in[4];
    const float* bu1 = (const float*)d_in[5];
    const float* Wu2 = (const float*)d_in[6];
    const float* bu2 = (const float*)d_in[7];
    const float* Wi1 = (const float*)d_in[8];
    const float* bi1 = (const float*)d_in[9];
    const float* Wi2 = (const float*)d_in[10];
    const float* bi2 = (const float*)d_in[11];
    const int* u_nbr = (const int*)d_in[12];
    const int* u_tim = (const int*)d_in[13];
    const int* i_nbr = (const int*)d_in[14];
    const int* i_tim = (const int*)d_in[15];
    float* out = (float*)d_out;

    dim3 gs((NROWS + 127) / 128, 2);
    te_dot_kernel<<<gs, 128>>>(user_h, item_h, u_te, i_te);
    attn_kernel<<<TOTROWS, 64>>>(user_h, item_h, u_nbr, u_tim, i_nbr, i_tim);
    mlp_kernel<<<gs, 128>>>(Wu1, bu1, Wu2, bu2, Wi1, bi1, Wi2, bi2, out);
}